// round 17
// baseline (speedup 1.0000x reference)
#include <cuda_runtime.h>

#define BB 64      // batch
#define SS 512     // sequence length
#define EE 256     // embedding dim
#define HH 512     // hidden
#define GG 2048    // 4*H gate rows

typedef unsigned long long u64;
typedef unsigned int u32;
typedef unsigned short u16;

// ---------------------------------------------------------------------------
// Device globals
// ---------------------------------------------------------------------------
__device__ u32 g_wf[128][32];                 // per-CTA flags (padded 128B lines)
__device__ float g_xg[SS * GG * BB];          // x_gates [s][g][b]
__device__ u16 g_hhi[4][BB * HH];             // h ring, bf16 hi, [b][k]
__device__ u16 g_hlo[4][BB * HH];             // h ring, bf16 lo, [b][k]

// ---------------------------------------------------------------------------
// helpers
// ---------------------------------------------------------------------------
__device__ __forceinline__ float sigf(float x) { return 1.f / (1.f + __expf(-x)); }
__device__ __forceinline__ float tanh_f(float x) { return 2.f / (1.f + __expf(-2.f * x)) - 1.f; }

__device__ __forceinline__ u16 f2bf(float x) {
    u16 r; asm("cvt.rn.bf16.f32 %0, %1;" : "=h"(r) : "f"(x)); return r;
}
__device__ __forceinline__ float bf2f(u16 b) {
    return __uint_as_float((u32)b << 16);
}
// packed bf16x2 convert: lo 16 bits = v0, hi 16 bits = v1
__device__ __forceinline__ u32 pack_bf2(float v0, float v1) {
    u32 d; asm("cvt.rn.bf16x2.f32 %0, %1, %2;" : "=r"(d) : "f"(v1), "f"(v0)); return d;
}
__device__ __forceinline__ void split_bf2(float v0, float v1, u32& hi, u32& lo) {
    hi = pack_bf2(v0, v1);
    float r0 = v0 - __uint_as_float(hi << 16);
    float r1 = v1 - __uint_as_float(hi & 0xffff0000u);
    lo = pack_bf2(r0, r1);
}

// mma.sync m16n8k16 bf16: D(f32) += A(bf16) * B(bf16)
__device__ __forceinline__ void mma_bf16(float* d, const u32* a, u32 b0, u32 b1) {
    asm volatile(
        "mma.sync.aligned.m16n8k16.row.col.f32.bf16.bf16.f32 "
        "{%0,%1,%2,%3}, {%4,%5,%6,%7}, {%8,%9}, {%0,%1,%2,%3};"
        : "+f"(d[0]), "+f"(d[1]), "+f"(d[2]), "+f"(d[3])
        : "r"(a[0]), "r"(a[1]), "r"(a[2]), "r"(a[3]), "r"(b0), "r"(b1));
}

// ---------------------------------------------------------------------------
// Phase A on tensor cores (R16, measured ~520us, unchanged)
// ---------------------------------------------------------------------------
#define WP   132
#define SCRP 65
#define OFF_WSL  (64 * WP)
#define OFF_SCR  (2 * 64 * WP)
#define OFF_BIA  (OFF_SCR + 128 * SCRP)
#define OFF_ROWS (OFF_BIA + 64)
#define OFF_IS64 (OFF_ROWS + 128)
#define GEMM_SMEM_U32 (OFF_IS64 + 1)

__global__ void __launch_bounds__(256) xgates_gemm(
    const void* __restrict__ seq,
    const float* __restrict__ emb,
    const float* __restrict__ Wih,
    const float* __restrict__ bih,
    const float* __restrict__ bhh)
{
    extern __shared__ u32 smu[];
    u32*   wsh   = smu;
    u32*   wsl   = smu + OFF_WSL;
    float* scr   = (float*)(smu + OFF_SCR);
    float* sbias = (float*)(smu + OFF_BIA);
    int*   rows  = (int*)(smu + OFF_ROWS);
    u32*   is64p = smu + OFF_IS64;

    const int tid  = threadIdx.x;
    const int wi   = tid >> 5;
    const int lane = tid & 31;
    const int gid  = lane >> 2;
    const int tig  = lane & 3;
    const int s0 = blockIdx.y * 2;
    const int g0 = blockIdx.x * 64;

    if (tid == 0) *is64p = 1;
    __syncthreads();
    if (tid < 64) {
        if (((const u32*)seq)[2 * tid + 1] != 0u) *is64p = 0;
    }
    __syncthreads();
    if (tid < 128) {
        int b = tid & 63, sl = tid >> 6;
        int idx;
        if (*is64p) idx = (int)((const long long*)seq)[b * SS + s0 + sl];
        else        idx = ((const int*)seq)[b * SS + s0 + sl];
        rows[tid] = idx;
    }

    {
        int n = tid >> 2, kseg = (tid & 3) * 64;
        const float* wr = Wih + (size_t)(g0 + n) * EE + kseg;
        #pragma unroll
        for (int i = 0; i < 16; i++) {
            float4 v = *(const float4*)(wr + i * 4);
            u32 h01, l01, h23, l23;
            split_bf2(v.x, v.y, h01, l01);
            split_bf2(v.z, v.w, h23, l23);
            int c = n * WP + ((kseg + i * 4) >> 1);
            wsh[c] = h01; wsh[c + 1] = h23;
            wsl[c] = l01; wsl[c + 1] = l23;
        }
    }
    if (tid < 64) sbias[tid] = bih[g0 + tid] + bhh[g0 + tid];
    __syncthreads();

    const int m0 = wi * 16 + gid;
    const float* e0 = emb + (size_t)rows[m0] * EE;
    const float* e1 = emb + (size_t)rows[m0 + 8] * EE;

    float C[8][4];
    #pragma unroll
    for (int nt = 0; nt < 8; nt++)
        #pragma unroll
        for (int q = 0; q < 4; q++) C[nt][q] = 0.f;

    #pragma unroll
    for (int kt = 0; kt < 16; kt++) {
        const int k0 = kt * 16 + tig * 2;
        float2 p00 = *(const float2*)(e0 + k0);
        float2 p10 = *(const float2*)(e1 + k0);
        float2 p01 = *(const float2*)(e0 + k0 + 8);
        float2 p11 = *(const float2*)(e1 + k0 + 8);
        u32 Ah[4], Al[4];
        split_bf2(p00.x, p00.y, Ah[0], Al[0]);
        split_bf2(p10.x, p10.y, Ah[1], Al[1]);
        split_bf2(p01.x, p01.y, Ah[2], Al[2]);
        split_bf2(p11.x, p11.y, Ah[3], Al[3]);

        const int kc = kt * 8 + tig;
        #pragma unroll
        for (int nt = 0; nt < 8; nt++) {
            int rb = (nt * 8 + gid) * WP + kc;
            u32 bh0 = wsh[rb], bh1 = wsh[rb + 4];
            u32 bl0 = wsl[rb], bl1 = wsl[rb + 4];
            mma_bf16(C[nt], Ah, bh0, bh1);
            mma_bf16(C[nt], Ah, bl0, bl1);
            mma_bf16(C[nt], Al, bh0, bh1);
        }
    }

    #pragma unroll
    for (int nt = 0; nt < 8; nt++) {
        int ncol = nt * 8 + tig * 2;
        scr[(wi * 16 + gid) * SCRP + ncol]     = C[nt][0];
        scr[(wi * 16 + gid) * SCRP + ncol + 1] = C[nt][1];
        scr[(wi * 16 + gid + 8) * SCRP + ncol]     = C[nt][2];
        scr[(wi * 16 + gid + 8) * SCRP + ncol + 1] = C[nt][3];
    }
    __syncthreads();

    {
        const int b = tid & 63, q = tid >> 6;
        const int sl = q & 1, gh = (q >> 1) * 32;
        const float* src = &scr[(sl * 64 + b) * SCRP];
        float* dst = &g_xg[(size_t)(s0 + sl) * (GG * BB) + (size_t)g0 * BB + b];
        #pragma unroll
        for (int gl = 0; gl < 32; gl++) {
            int g = gh + gl;
            dst[(size_t)g * BB] = src[g] + sbias[g];
        }
    }
}

// ---------------------------------------------------------------------------
// Phase B: WARP-AUTONOMOUS tensor-core LSTM recurrence.
// 128 CTAs x 256 threads (8 warps). CTA owns 4 h-columns -> 16 gate rows
// (M). Warp wi owns b-columns [wi*8,+8) (N=8) x FULL K=512: no k-split,
// no cross-warp reduce, ZERO per-step __syncthreads. Per step per warp:
//   poll all 128 CTA flags (4/lane, target base+8s) -> B-frags direct LDG
//   from bf16 hi/lo rings [b][k] (each k-tile row = one 32B sector) ->
//   96 HMMA (hh+hl+lh, fp32 acc) with A-frags LDS.128 from pre-swizzled
//   SMEM W image -> per-warp 16x8 transpose (syncwarp) -> gates ->
//   h hi/lo store -> per-warp red.release bump (+8/CTA/step).
// Ring depth 4: join(s-1) covers all warps' step s-3 reads -> reuse safe.
// ---------------------------------------------------------------------------
#define LW_SCR_STRIDE 10    // f32 per transpose row
#define LW_OFF_SCR (8192)   // u32 offset: Whi_sw 4096 + Wlo_sw 4096
#define LSTM_SMEM_U32 (LW_OFF_SCR + 8 * 16 * LW_SCR_STRIDE)

__global__ void __launch_bounds__(256, 1) lstm_kernel(
    const float* __restrict__ Whh, float* __restrict__ out, int write_c)
{
    extern __shared__ u32 smu[];
    u32*   whi = smu;                        // [(kt*32+lane)*4+q]
    u32*   wlo = smu + 4096;
    float* scr = (float*)(smu + LW_OFF_SCR); // [warp][16][LW_SCR_STRIDE]
    __shared__ u32 s_base;

    const int tid  = threadIdx.x;
    const int wi   = tid >> 5;
    const int lane = tid & 31;
    const int gid  = lane >> 2;
    const int tig  = lane & 3;
    const int cta  = blockIdx.x;
    const int j0   = cta * 4;

    if (tid == 0) s_base = g_wf[cta][0];

    // ---- stage W_hh hi/lo as pre-swizzled A-fragments (once) ----
    #pragma unroll
    for (int i = 0; i < 4; i++) {
        int kt = wi * 4 + i;
        #pragma unroll
        for (int q = 0; q < 4; q++) {
            int r  = (q & 1) ? gid + 8 : gid;
            int k  = kt * 16 + tig * 2 + ((q >> 1) ? 8 : 0);
            int grow = (r >> 2) * HH + j0 + (r & 3);
            float w0 = Whh[(size_t)grow * HH + k];
            float w1 = Whh[(size_t)grow * HH + k + 1];
            u32 hi, lo;
            split_bf2(w0, w1, hi, lo);
            whi[(kt * 32 + lane) * 4 + q] = hi;
            wlo[(kt * 32 + lane) * 4 + q] = lo;
        }
    }
    __syncthreads();   // the only block-wide sync

    const int b  = wi * 8 + (lane >> 2);    // this lane's (b, j)
    const int jl = lane & 3;
    const int j  = j0 + jl;
    const u32 base = s_base;
    float* wscr = &scr[wi * 16 * LW_SCR_STRIDE];

    float c_reg = 0.f, h_val = 0.f;

    #pragma unroll 1
    for (int s = 0; s < SS; s++) {
        // xg (precomputed, no sync needed) -- overlaps the poll
        float xgv[4];
        const float* xgs = g_xg + (size_t)s * (GG * BB);
        #pragma unroll
        for (int g = 0; g < 4; g++)
            xgv[g] = __ldg(&xgs[(g * HH + j) * BB + b]);

        float gt[4];

        if (s > 0) {
            // ---- full join: all 128 producer CTAs at step s-1 (4 flags/lane)
            const u32 target = base + 8u * (u32)s;
            int ok, first = 1;
            do {
                if (!first) __nanosleep(20);
                first = 0;
                ok = 1;
                #pragma unroll
                for (int q = 0; q < 4; q++) {
                    u32 f;
                    asm volatile("ld.acquire.gpu.global.u32 %0, [%1];"
                                 : "=r"(f) : "l"(&g_wf[lane + q * 32][0]));
                    ok &= ((int)(f - target) >= 0);
                }
            } while (__all_sync(0xffffffffu, ok) == 0);

            const u32* rh = (const u32*)g_hhi[(s - 1) & 3];   // [b][k] pairs
            const u32* rl = (const u32*)g_hlo[(s - 1) & 3];
            const int bn  = wi * 8 + gid;                      // n-col b row
            const int bidx0 = bn * 256 + tig;                  // u32 base

            float C[4] = {0.f, 0.f, 0.f, 0.f};

            #pragma unroll 8
            for (int kt = 0; kt < 32; kt++) {
                // B-frags: (k, k+1) and (k+8, k+9) of row bn
                int bi = bidx0 + kt * 8;
                u32 bh0 = __ldcg(&rh[bi]);
                u32 bh1 = __ldcg(&rh[bi + 4]);
                u32 bl0 = __ldcg(&rl[bi]);
                u32 bl1 = __ldcg(&rl[bi + 4]);
                // A-frags from pre-swizzled SMEM
                uint4 ah = *(const uint4*)&whi[(kt * 32 + lane) * 4];
                uint4 al = *(const uint4*)&wlo[(kt * 32 + lane) * 4];
                mma_bf16(C, (const u32*)&ah, bh0, bh1);   // hi*hi
                mma_bf16(C, (const u32*)&ah, bl0, bl1);   // hi*lo
                mma_bf16(C, (const u32*)&al, bh0, bh1);   // lo*hi
            }

            // ---- per-warp transpose: C frags -> [r][bcol] ----
            *(float2*)&wscr[gid * LW_SCR_STRIDE + 2 * tig] =
                make_float2(C[0], C[1]);
            *(float2*)&wscr[(gid + 8) * LW_SCR_STRIDE + 2 * tig] =
                make_float2(C[2], C[3]);
            __syncwarp();

            const int bl_r = lane >> 2;
            #pragma unroll
            for (int g = 0; g < 4; g++)
                gt[g] = wscr[(g * 4 + jl) * LW_SCR_STRIDE + bl_r] + xgv[g];
            __syncwarp();
        } else {
            #pragma unroll
            for (int g = 0; g < 4; g++) gt[g] = xgv[g];
        }

        // ---- gates, state update ----
        float ig = sigf(gt[0]), fg = sigf(gt[1]);
        float gg = tanh_f(gt[2]), og = sigf(gt[3]);
        c_reg = fg * c_reg + ig * gg;
        h_val = og * tanh_f(c_reg);

        // ---- h -> bf16 hi/lo rings [b][k] ----
        {
            u16 hi = f2bf(h_val);
            u16 lo = f2bf(h_val - bf2f(hi));
            g_hhi[s & 3][b * HH + j] = hi;
            g_hlo[s & 3][b * HH + j] = lo;
        }
        __syncwarp();   // warp's 32 (b,j) stores done before its bump
        if (lane == 0) {
            asm volatile("red.release.gpu.global.add.u32 [%0], %1;"
                         :: "l"(&g_wf[cta][0]), "r"(1u) : "memory");
        }
    }

    out[b * HH + j] = h_val;
    if (write_c) out[BB * HH + b * HH + j] = c_reg;
}

// ---------------------------------------------------------------------------
// kernel_launch
// ---------------------------------------------------------------------------
extern "C" void kernel_launch(void* const* d_in, const int* in_sizes, int n_in,
                              void* d_out, int out_size)
{
    const void*  seq = d_in[0];
    const float* emb = (const float*)d_in[1];
    const float* Wih = (const float*)d_in[2];
    const float* Whh = (const float*)d_in[3];
    const float* bih = (const float*)d_in[4];
    const float* bhh = (const float*)d_in[5];
    float* out = (float*)d_out;

    (void)in_sizes; (void)n_in;
    int write_c = (out_size >= 2 * BB * HH) ? 1 : 0;

    static const int kGemmSmem = GEMM_SMEM_U32 * 4;     // ~101 KB
    static const int kLstmSmem = LSTM_SMEM_U32 * 4;     // ~38 KB
    cudaFuncSetAttribute(xgates_gemm, cudaFuncAttributeMaxDynamicSharedMemorySize, kGemmSmem);
    cudaFuncSetAttribute(lstm_kernel, cudaFuncAttributeMaxDynamicSharedMemorySize, kLstmSmem);

    xgates_gemm<<<dim3(GG / 64, SS / 2), 256, kGemmSmem>>>(seq, emb, Wih, bih, bhh);
    lstm_kernel<<<HH / 4, 256, kLstmSmem>>>(Whh, out, write_c);
}